// round 9
// baseline (speedup 1.0000x reference)
#include <cuda_runtime.h>
#include <cstdint>

// Problem constants
#define B_    8
#define CIN   32
#define COUT  32
#define HH    512
#define WW    512
#define KK    3
#define SDIM  512

#define TW 16          // tile width (output cols per block)
#define TH 32          // tile height (output rows per block)
#define THREADS 256    // 16 x 16 threads, each thread: 1 col x 2 rows x 32 couts

#define XT_W (TW + 2)          // 18
#define XT_H (TH + 2)          // 34
#define XT_PER_CIN (XT_H * XT_W)   // 612
#define XT_TOTAL (CIN * XT_PER_CIN) // 19584 floats
#define W_TOTAL (CIN * 9 * COUT)    // 9216 floats per sample
#define SMEM_FLOATS (XT_TOTAL + W_TOTAL)
#define SMEM_BYTES (SMEM_FLOATS * 4)  // 115200

// Scratch: per-sample modulated+demodulated weights, layout [b][cin*9+tap][cout]
__device__ float g_wmod[B_ * W_TOTAL];

// ---------------------------------------------------------------------------
// Prep kernel: style modulation -> weight modulation -> demod -> g_wmod
// One block per batch sample.
// ---------------------------------------------------------------------------
__global__ void __launch_bounds__(256) modconv_prep(
    const float* __restrict__ style,   // [B, SDIM]
    const float* __restrict__ weight,  // [1, COUT, CIN, 3, 3]
    const float* __restrict__ mod_w,   // [CIN, SDIM]
    const float* __restrict__ mod_b)   // [CIN]
{
    const int b = blockIdx.x;
    const int t = threadIdx.x;

    __shared__ float s_sh[CIN];
    __shared__ float w_sh[COUT * 288];   // [cout][cin*9+tap]
    __shared__ float demod_sh[COUT];

    const float mod_scale  = 0.044194173824159216f;  // 1/sqrt(512)
    const float conv_scale = 0.05892556509887896f;   // 1/sqrt(288)

    // Stage 1: s[cin] = (style[b] . mod_w[cin]) * mod_scale + mod_b[cin]
    {
        const int cin = t >> 3;       // 32 groups of 8 threads
        const int l   = t & 7;
        float acc = 0.f;
        const float* sp = style + b * SDIM;
        const float* mp = mod_w + cin * SDIM;
        for (int j = l; j < SDIM; j += 8)
            acc += sp[j] * mp[j];
        #pragma unroll
        for (int o = 4; o > 0; o >>= 1)
            acc += __shfl_xor_sync(0xffffffffu, acc, o);
        if (l == 0)
            s_sh[cin] = acc * mod_scale + mod_b[cin];
    }
    __syncthreads();

    // Stage 2: modulate + sum of squares per cout
    {
        const int cout = t >> 3;
        const int l    = t & 7;
        float ss = 0.f;
        const float* wp = weight + cout * 288;
        for (int e = l; e < 288; e += 8) {
            const int ci = e / 9;
            float wv = conv_scale * wp[e] * s_sh[ci];
            w_sh[cout * 288 + e] = wv;
            ss += wv * wv;
        }
        #pragma unroll
        for (int o = 4; o > 0; o >>= 1)
            ss += __shfl_xor_sync(0xffffffffu, ss, o);
        if (l == 0)
            demod_sh[cout] = rsqrtf(ss + 1e-8f);
    }
    __syncthreads();

    // Stage 3: write [cin*9+tap][cout] layout scaled by demod
    float* gw = g_wmod + b * W_TOTAL;
    for (int i = t; i < W_TOTAL; i += 256) {
        const int cout = i & 31;
        const int ct   = i >> 5;     // cin*9 + tap
        gw[i] = w_sh[cout * 288 + ct] * demod_sh[cout];
    }
}

// ---------------------------------------------------------------------------
// Conv kernel. Per-thread: 1 output column x 2 adjacent rows x 32 couts.
// Accumulators packed as f32x2 (fma.rn.f32x2 -> SASS FFMA2, 2 MACs/instr).
// ---------------------------------------------------------------------------
__global__ void __launch_bounds__(THREADS, 1) modconv_main(
    const float* __restrict__ x,   // [B, CIN, H, W]
    float* __restrict__ out)       // [B, COUT, H, W]
{
    extern __shared__ float sm[];
    float* xs = sm;                // input tile [cin][34][18]
    float* ws = sm + XT_TOTAL;     // weights [cin][tap][cout]

    const int b  = blockIdx.z;
    const int x0 = blockIdx.x * TW;
    const int y0 = blockIdx.y * TH;
    const int t  = threadIdx.x;

    // --- stage weights (broadcast-read later) ---
    {
        const float* wg = g_wmod + b * W_TOTAL;
        #pragma unroll
        for (int i = t; i < W_TOTAL; i += THREADS)
            ws[i] = wg[i];
    }

    // --- stage input tile with halo (zero-padded) ---
    {
        const float* xb = x + (size_t)b * CIN * HH * WW;
        for (int i = t; i < XT_TOTAL; i += THREADS) {
            const int cin = i / XT_PER_CIN;
            const int r   = i - cin * XT_PER_CIN;
            const int yy  = r / XT_W;
            const int xx  = r - yy * XT_W;
            const int gy  = y0 - 1 + yy;
            const int gx  = x0 - 1 + xx;
            float v = 0.f;
            if ((unsigned)gy < (unsigned)HH && (unsigned)gx < (unsigned)WW)
                v = xb[(cin * HH + gy) * WW + gx];
            xs[i] = v;
        }
    }
    __syncthreads();

    const int tx = t & 15;
    const int ty = t >> 4;

    // acc0[m] = couts (2m, 2m+1) for output row gy0; acc1 same for gy0+1
    unsigned long long acc0[16], acc1[16];
    #pragma unroll
    for (int q = 0; q < 16; ++q) { acc0[q] = 0ull; acc1[q] = 0ull; }

    #pragma unroll 1
    for (int cin = 0; cin < CIN; ++cin) {
        // x values: tile rows ty*2 .. ty*2+3, cols tx .. tx+2
        const float* xp = xs + cin * XT_PER_CIN + (ty * 2) * XT_W + tx;
        unsigned long long xv[4][3];
        #pragma unroll
        for (int r = 0; r < 4; ++r) {
            #pragma unroll
            for (int c = 0; c < 3; ++c) {
                const unsigned u = __float_as_uint(xp[r * XT_W + c]);
                asm("mov.b64 %0, {%1, %1};" : "=l"(xv[r][c]) : "r"(u));
            }
        }

        const ulonglong2* wp = (const ulonglong2*)(ws + cin * 288);
        #pragma unroll
        for (int tap = 0; tap < 9; ++tap) {
            const int dy = tap / 3;
            const int dx = tap % 3;
            const unsigned long long xa = xv[dy][dx];       // pixel 0
            const unsigned long long xb2 = xv[dy + 1][dx];  // pixel 1
            #pragma unroll
            for (int q = 0; q < 8; ++q) {
                const ulonglong2 wv = wp[tap * 8 + q];  // couts 4q..4q+3
                asm("fma.rn.f32x2 %0, %1, %2, %0;" : "+l"(acc0[2*q])   : "l"(xa),  "l"(wv.x));
                asm("fma.rn.f32x2 %0, %1, %2, %0;" : "+l"(acc0[2*q+1]) : "l"(xa),  "l"(wv.y));
                asm("fma.rn.f32x2 %0, %1, %2, %0;" : "+l"(acc1[2*q])   : "l"(xb2), "l"(wv.x));
                asm("fma.rn.f32x2 %0, %1, %2, %0;" : "+l"(acc1[2*q+1]) : "l"(xb2), "l"(wv.y));
            }
        }
    }

    // --- write out ---
    const int gy0 = y0 + ty * 2;
    const int gx  = x0 + tx;
    float* ob = out + (size_t)b * COUT * HH * WW;
    #pragma unroll
    for (int q = 0; q < 16; ++q) {
        unsigned lo, hi;
        asm("mov.b64 {%0, %1}, %2;" : "=r"(lo), "=r"(hi) : "l"(acc0[q]));
        ob[((2*q)     * HH + gy0) * WW + gx] = __uint_as_float(lo);
        ob[((2*q + 1) * HH + gy0) * WW + gx] = __uint_as_float(hi);
        asm("mov.b64 {%0, %1}, %2;" : "=r"(lo), "=r"(hi) : "l"(acc1[q]));
        ob[((2*q)     * HH + gy0 + 1) * WW + gx] = __uint_as_float(lo);
        ob[((2*q + 1) * HH + gy0 + 1) * WW + gx] = __uint_as_float(hi);
    }
}

// ---------------------------------------------------------------------------
// Launch
// ---------------------------------------------------------------------------
extern "C" void kernel_launch(void* const* d_in, const int* in_sizes, int n_in,
                              void* d_out, int out_size)
{
    const float* x      = (const float*)d_in[0];  // [8,32,512,512]
    const float* style  = (const float*)d_in[1];  // [8,512]
    const float* weight = (const float*)d_in[2];  // [1,32,32,3,3]
    const float* mod_w  = (const float*)d_in[3];  // [32,512]
    const float* mod_b  = (const float*)d_in[4];  // [32]
    float* out = (float*)d_out;

    // Opt-in to >48KB dynamic smem (idempotent, legal during graph capture).
    cudaFuncSetAttribute(modconv_main,
                         cudaFuncAttributeMaxDynamicSharedMemorySize, SMEM_BYTES);

    modconv_prep<<<B_, 256>>>(style, weight, mod_w, mod_b);

    dim3 grid(WW / TW, HH / TH, B_);   // 32 x 16 x 8 = 4096 blocks
    modconv_main<<<grid, THREADS, SMEM_BYTES>>>(x, out);
}

// round 10
// speedup vs baseline: 1.0069x; 1.0069x over previous
#include <cuda_runtime.h>
#include <cstdint>

// Problem constants
#define B_    8
#define CIN   32
#define COUT  32
#define HH    512
#define WW    512
#define KK    3
#define SDIM  512

#define TW 16          // tile width (output cols per block)
#define TH 32          // tile height (output rows per block)
#define THREADS 256    // 16 x 16 threads, each thread: 1 col x 2 rows x 32 couts

#define XT_W (TW + 2)          // 18
#define XT_H (TH + 2)          // 34
#define XT_PER_CIN (XT_H * XT_W)   // 612
#define XT_TOTAL (CIN * XT_PER_CIN) // 19584 floats
#define W_TOTAL (CIN * 9 * COUT)    // 9216 floats per sample
#define SMEM_FLOATS (XT_TOTAL + W_TOTAL)
#define SMEM_BYTES (SMEM_FLOATS * 4)  // 115200

// Scratch: per-sample modulated+demodulated weights, layout [b][cin*9+tap][cout]
__device__ float g_wmod[B_ * W_TOTAL];

// ---------------------------------------------------------------------------
// Prep kernel: style modulation -> weight modulation -> demod -> g_wmod
// One block per batch sample.
// ---------------------------------------------------------------------------
__global__ void __launch_bounds__(256) modconv_prep(
    const float* __restrict__ style,   // [B, SDIM]
    const float* __restrict__ weight,  // [1, COUT, CIN, 3, 3]
    const float* __restrict__ mod_w,   // [CIN, SDIM]
    const float* __restrict__ mod_b)   // [CIN]
{
    const int b = blockIdx.x;
    const int t = threadIdx.x;

    __shared__ float s_sh[CIN];
    __shared__ float w_sh[COUT * 288];   // [cout][cin*9+tap]
    __shared__ float demod_sh[COUT];

    const float mod_scale  = 0.044194173824159216f;  // 1/sqrt(512)
    const float conv_scale = 0.05892556509887896f;   // 1/sqrt(288)

    // Stage 1: s[cin] = (style[b] . mod_w[cin]) * mod_scale + mod_b[cin]
    {
        const int cin = t >> 3;       // 32 groups of 8 threads
        const int l   = t & 7;
        float acc = 0.f;
        const float* sp = style + b * SDIM;
        const float* mp = mod_w + cin * SDIM;
        for (int j = l; j < SDIM; j += 8)
            acc += sp[j] * mp[j];
        #pragma unroll
        for (int o = 4; o > 0; o >>= 1)
            acc += __shfl_xor_sync(0xffffffffu, acc, o);
        if (l == 0)
            s_sh[cin] = acc * mod_scale + mod_b[cin];
    }
    __syncthreads();

    // Stage 2: modulate + sum of squares per cout
    {
        const int cout = t >> 3;
        const int l    = t & 7;
        float ss = 0.f;
        const float* wp = weight + cout * 288;
        for (int e = l; e < 288; e += 8) {
            const int ci = e / 9;
            float wv = conv_scale * wp[e] * s_sh[ci];
            w_sh[cout * 288 + e] = wv;
            ss += wv * wv;
        }
        #pragma unroll
        for (int o = 4; o > 0; o >>= 1)
            ss += __shfl_xor_sync(0xffffffffu, ss, o);
        if (l == 0)
            demod_sh[cout] = rsqrtf(ss + 1e-8f);
    }
    __syncthreads();

    // Stage 3: write [cin*9+tap][cout] layout scaled by demod
    float* gw = g_wmod + b * W_TOTAL;
    for (int i = t; i < W_TOTAL; i += 256) {
        const int cout = i & 31;
        const int ct   = i >> 5;     // cin*9 + tap
        gw[i] = w_sh[cout * 288 + ct] * demod_sh[cout];
    }
}

// ---------------------------------------------------------------------------
// Conv kernel. Per-thread: 1 output column x 2 adjacent rows x 32 couts.
// Accumulators packed as f32x2 (fma.rn.f32x2 -> SASS FFMA2, 2 MACs/instr).
// ---------------------------------------------------------------------------
__global__ void __launch_bounds__(THREADS, 1) modconv_main(
    const float* __restrict__ x,   // [B, CIN, H, W]
    float* __restrict__ out)       // [B, COUT, H, W]
{
    extern __shared__ float sm[];
    float* xs = sm;                // input tile [cin][34][18]
    float* ws = sm + XT_TOTAL;     // weights [cin][tap][cout]

    const int b  = blockIdx.z;
    const int x0 = blockIdx.x * TW;
    const int y0 = blockIdx.y * TH;
    const int t  = threadIdx.x;

    // --- stage weights (broadcast-read later) ---
    {
        const float* wg = g_wmod + b * W_TOTAL;
        #pragma unroll
        for (int i = t; i < W_TOTAL; i += THREADS)
            ws[i] = wg[i];
    }

    // --- stage input tile with halo (zero-padded) ---
    {
        const float* xb = x + (size_t)b * CIN * HH * WW;
        for (int i = t; i < XT_TOTAL; i += THREADS) {
            const int cin = i / XT_PER_CIN;
            const int r   = i - cin * XT_PER_CIN;
            const int yy  = r / XT_W;
            const int xx  = r - yy * XT_W;
            const int gy  = y0 - 1 + yy;
            const int gx  = x0 - 1 + xx;
            float v = 0.f;
            if ((unsigned)gy < (unsigned)HH && (unsigned)gx < (unsigned)WW)
                v = xb[(cin * HH + gy) * WW + gx];
            xs[i] = v;
        }
    }
    __syncthreads();

    const int tx = t & 15;
    const int ty = t >> 4;

    // acc0[m] = couts (2m, 2m+1) for output row gy0; acc1 same for gy0+1
    unsigned long long acc0[16], acc1[16];
    #pragma unroll
    for (int q = 0; q < 16; ++q) { acc0[q] = 0ull; acc1[q] = 0ull; }

    #pragma unroll 1
    for (int cin = 0; cin < CIN; ++cin) {
        // x values: tile rows ty*2 .. ty*2+3, cols tx .. tx+2
        const float* xp = xs + cin * XT_PER_CIN + (ty * 2) * XT_W + tx;
        unsigned long long xv[4][3];
        #pragma unroll
        for (int r = 0; r < 4; ++r) {
            #pragma unroll
            for (int c = 0; c < 3; ++c) {
                const unsigned u = __float_as_uint(xp[r * XT_W + c]);
                asm("mov.b64 %0, {%1, %1};" : "=l"(xv[r][c]) : "r"(u));
            }
        }

        const ulonglong2* wp = (const ulonglong2*)(ws + cin * 288);
        #pragma unroll
        for (int tap = 0; tap < 9; ++tap) {
            const int dy = tap / 3;
            const int dx = tap % 3;
            const unsigned long long xa = xv[dy][dx];       // pixel 0
            const unsigned long long xb2 = xv[dy + 1][dx];  // pixel 1
            #pragma unroll
            for (int q = 0; q < 8; ++q) {
                const ulonglong2 wv = wp[tap * 8 + q];  // couts 4q..4q+3
                asm("fma.rn.f32x2 %0, %1, %2, %0;" : "+l"(acc0[2*q])   : "l"(xa),  "l"(wv.x));
                asm("fma.rn.f32x2 %0, %1, %2, %0;" : "+l"(acc0[2*q+1]) : "l"(xa),  "l"(wv.y));
                asm("fma.rn.f32x2 %0, %1, %2, %0;" : "+l"(acc1[2*q])   : "l"(xb2), "l"(wv.x));
                asm("fma.rn.f32x2 %0, %1, %2, %0;" : "+l"(acc1[2*q+1]) : "l"(xb2), "l"(wv.y));
            }
        }
    }

    // --- write out ---
    const int gy0 = y0 + ty * 2;
    const int gx  = x0 + tx;
    float* ob = out + (size_t)b * COUT * HH * WW;
    #pragma unroll
    for (int q = 0; q < 16; ++q) {
        unsigned lo, hi;
        asm("mov.b64 {%0, %1}, %2;" : "=r"(lo), "=r"(hi) : "l"(acc0[q]));
        ob[((2*q)     * HH + gy0) * WW + gx] = __uint_as_float(lo);
        ob[((2*q + 1) * HH + gy0) * WW + gx] = __uint_as_float(hi);
        asm("mov.b64 {%0, %1}, %2;" : "=r"(lo), "=r"(hi) : "l"(acc1[q]));
        ob[((2*q)     * HH + gy0 + 1) * WW + gx] = __uint_as_float(lo);
        ob[((2*q + 1) * HH + gy0 + 1) * WW + gx] = __uint_as_float(hi);
    }
}

// ---------------------------------------------------------------------------
// Launch
// ---------------------------------------------------------------------------
extern "C" void kernel_launch(void* const* d_in, const int* in_sizes, int n_in,
                              void* d_out, int out_size)
{
    const float* x      = (const float*)d_in[0];  // [8,32,512,512]
    const float* style  = (const float*)d_in[1];  // [8,512]
    const float* weight = (const float*)d_in[2];  // [1,32,32,3,3]
    const float* mod_w  = (const float*)d_in[3];  // [32,512]
    const float* mod_b  = (const float*)d_in[4];  // [32]
    float* out = (float*)d_out;

    // Opt-in to >48KB dynamic smem (idempotent, legal during graph capture).
    cudaFuncSetAttribute(modconv_main,
                         cudaFuncAttributeMaxDynamicSharedMemorySize, SMEM_BYTES);

    modconv_prep<<<B_, 256>>>(style, weight, mod_w, mod_b);

    dim3 grid(WW / TW, HH / TH, B_);   // 32 x 16 x 8 = 4096 blocks
    modconv_main<<<grid, THREADS, SMEM_BYTES>>>(x, out);
}

// round 11
// speedup vs baseline: 1.0097x; 1.0028x over previous
#include <cuda_runtime.h>
#include <cstdint>

// Problem constants
#define B_    8
#define CIN   32
#define COUT  32
#define HH    512
#define WW    512
#define KK    3
#define SDIM  512

#define TW 16          // tile width (output cols per block)
#define TH 32          // tile height (output rows per block)
#define THREADS 256    // 16 x 16 threads, each thread: 1 col x 2 rows x 32 couts

#define XT_W (TW + 2)          // 18
#define XT_H (TH + 2)          // 34
#define XT_PER_CIN (XT_H * XT_W)   // 612
#define XT_TOTAL (CIN * XT_PER_CIN) // 19584 floats
#define W_TOTAL (CIN * 9 * COUT)    // 9216 floats per sample
#define SMEM_FLOATS (XT_TOTAL + W_TOTAL)
#define SMEM_BYTES (SMEM_FLOATS * 4)  // 115200

// Scratch: per-sample modulated+demodulated weights, layout [b][cin*9+tap][cout]
__device__ float g_wmod[B_ * W_TOTAL];

// ---------------------------------------------------------------------------
// Prep kernel: style modulation -> weight modulation -> demod -> g_wmod
// One block per batch sample.
// ---------------------------------------------------------------------------
__global__ void __launch_bounds__(256) modconv_prep(
    const float* __restrict__ style,   // [B, SDIM]
    const float* __restrict__ weight,  // [1, COUT, CIN, 3, 3]
    const float* __restrict__ mod_w,   // [CIN, SDIM]
    const float* __restrict__ mod_b)   // [CIN]
{
    const int b = blockIdx.x;
    const int t = threadIdx.x;

    __shared__ float s_sh[CIN];
    __shared__ float w_sh[COUT * 288];   // [cout][cin*9+tap]
    __shared__ float demod_sh[COUT];

    const float mod_scale  = 0.044194173824159216f;  // 1/sqrt(512)
    const float conv_scale = 0.05892556509887896f;   // 1/sqrt(288)

    // Stage 1: s[cin] = (style[b] . mod_w[cin]) * mod_scale + mod_b[cin]
    {
        const int cin = t >> 3;       // 32 groups of 8 threads
        const int l   = t & 7;
        float acc = 0.f;
        const float* sp = style + b * SDIM;
        const float* mp = mod_w + cin * SDIM;
        for (int j = l; j < SDIM; j += 8)
            acc += sp[j] * mp[j];
        #pragma unroll
        for (int o = 4; o > 0; o >>= 1)
            acc += __shfl_xor_sync(0xffffffffu, acc, o);
        if (l == 0)
            s_sh[cin] = acc * mod_scale + mod_b[cin];
    }
    __syncthreads();

    // Stage 2: modulate + sum of squares per cout
    {
        const int cout = t >> 3;
        const int l    = t & 7;
        float ss = 0.f;
        const float* wp = weight + cout * 288;
        for (int e = l; e < 288; e += 8) {
            const int ci = e / 9;
            float wv = conv_scale * wp[e] * s_sh[ci];
            w_sh[cout * 288 + e] = wv;
            ss += wv * wv;
        }
        #pragma unroll
        for (int o = 4; o > 0; o >>= 1)
            ss += __shfl_xor_sync(0xffffffffu, ss, o);
        if (l == 0)
            demod_sh[cout] = rsqrtf(ss + 1e-8f);
    }
    __syncthreads();

    // Stage 3: write [cin*9+tap][cout] layout scaled by demod
    float* gw = g_wmod + b * W_TOTAL;
    for (int i = t; i < W_TOTAL; i += 256) {
        const int cout = i & 31;
        const int ct   = i >> 5;     // cin*9 + tap
        gw[i] = w_sh[cout * 288 + ct] * demod_sh[cout];
    }
}

// ---------------------------------------------------------------------------
// Conv kernel. Per-thread: 1 output column x 2 adjacent rows x 32 couts.
// Accumulators packed as f32x2 (fma.rn.f32x2 -> SASS FFMA2, 2 MACs/instr).
// ---------------------------------------------------------------------------
__global__ void __launch_bounds__(THREADS, 1) modconv_main(
    const float* __restrict__ x,   // [B, CIN, H, W]
    float* __restrict__ out)       // [B, COUT, H, W]
{
    extern __shared__ float sm[];
    float* xs = sm;                // input tile [cin][34][18]
    float* ws = sm + XT_TOTAL;     // weights [cin][tap][cout]

    const int b  = blockIdx.z;
    const int x0 = blockIdx.x * TW;
    const int y0 = blockIdx.y * TH;
    const int t  = threadIdx.x;

    // --- stage weights (broadcast-read later) ---
    {
        const float* wg = g_wmod + b * W_TOTAL;
        #pragma unroll
        for (int i = t; i < W_TOTAL; i += THREADS)
            ws[i] = wg[i];
    }

    // --- stage input tile with halo (zero-padded) ---
    {
        const float* xb = x + (size_t)b * CIN * HH * WW;
        for (int i = t; i < XT_TOTAL; i += THREADS) {
            const int cin = i / XT_PER_CIN;
            const int r   = i - cin * XT_PER_CIN;
            const int yy  = r / XT_W;
            const int xx  = r - yy * XT_W;
            const int gy  = y0 - 1 + yy;
            const int gx  = x0 - 1 + xx;
            float v = 0.f;
            if ((unsigned)gy < (unsigned)HH && (unsigned)gx < (unsigned)WW)
                v = xb[(cin * HH + gy) * WW + gx];
            xs[i] = v;
        }
    }
    __syncthreads();

    const int tx = t & 15;
    const int ty = t >> 4;

    // acc0[m] = couts (2m, 2m+1) for output row gy0; acc1 same for gy0+1
    unsigned long long acc0[16], acc1[16];
    #pragma unroll
    for (int q = 0; q < 16; ++q) { acc0[q] = 0ull; acc1[q] = 0ull; }

    #pragma unroll 1
    for (int cin = 0; cin < CIN; ++cin) {
        // x values: tile rows ty*2 .. ty*2+3, cols tx .. tx+2
        const float* xp = xs + cin * XT_PER_CIN + (ty * 2) * XT_W + tx;
        unsigned long long xv[4][3];
        #pragma unroll
        for (int r = 0; r < 4; ++r) {
            #pragma unroll
            for (int c = 0; c < 3; ++c) {
                const unsigned u = __float_as_uint(xp[r * XT_W + c]);
                asm("mov.b64 %0, {%1, %1};" : "=l"(xv[r][c]) : "r"(u));
            }
        }

        const ulonglong2* wp = (const ulonglong2*)(ws + cin * 288);
        #pragma unroll
        for (int tap = 0; tap < 9; ++tap) {
            const int dy = tap / 3;
            const int dx = tap % 3;
            const unsigned long long xa = xv[dy][dx];       // pixel 0
            const unsigned long long xb2 = xv[dy + 1][dx];  // pixel 1
            #pragma unroll
            for (int q = 0; q < 8; ++q) {
                const ulonglong2 wv = wp[tap * 8 + q];  // couts 4q..4q+3
                asm("fma.rn.f32x2 %0, %1, %2, %0;" : "+l"(acc0[2*q])   : "l"(xa),  "l"(wv.x));
                asm("fma.rn.f32x2 %0, %1, %2, %0;" : "+l"(acc0[2*q+1]) : "l"(xa),  "l"(wv.y));
                asm("fma.rn.f32x2 %0, %1, %2, %0;" : "+l"(acc1[2*q])   : "l"(xb2), "l"(wv.x));
                asm("fma.rn.f32x2 %0, %1, %2, %0;" : "+l"(acc1[2*q+1]) : "l"(xb2), "l"(wv.y));
            }
        }
    }

    // --- write out ---
    const int gy0 = y0 + ty * 2;
    const int gx  = x0 + tx;
    float* ob = out + (size_t)b * COUT * HH * WW;
    #pragma unroll
    for (int q = 0; q < 16; ++q) {
        unsigned lo, hi;
        asm("mov.b64 {%0, %1}, %2;" : "=r"(lo), "=r"(hi) : "l"(acc0[q]));
        ob[((2*q)     * HH + gy0) * WW + gx] = __uint_as_float(lo);
        ob[((2*q + 1) * HH + gy0) * WW + gx] = __uint_as_float(hi);
        asm("mov.b64 {%0, %1}, %2;" : "=r"(lo), "=r"(hi) : "l"(acc1[q]));
        ob[((2*q)     * HH + gy0 + 1) * WW + gx] = __uint_as_float(lo);
        ob[((2*q + 1) * HH + gy0 + 1) * WW + gx] = __uint_as_float(hi);
    }
}

// ---------------------------------------------------------------------------
// Launch
// ---------------------------------------------------------------------------
extern "C" void kernel_launch(void* const* d_in, const int* in_sizes, int n_in,
                              void* d_out, int out_size)
{
    const float* x      = (const float*)d_in[0];  // [8,32,512,512]
    const float* style  = (const float*)d_in[1];  // [8,512]
    const float* weight = (const float*)d_in[2];  // [1,32,32,3,3]
    const float* mod_w  = (const float*)d_in[3];  // [32,512]
    const float* mod_b  = (const float*)d_in[4];  // [32]
    float* out = (float*)d_out;

    // Opt-in to >48KB dynamic smem (idempotent, legal during graph capture).
    cudaFuncSetAttribute(modconv_main,
                         cudaFuncAttributeMaxDynamicSharedMemorySize, SMEM_BYTES);

    modconv_prep<<<B_, 256>>>(style, weight, mod_w, mod_b);

    dim3 grid(WW / TW, HH / TH, B_);   // 32 x 16 x 8 = 4096 blocks
    modconv_main<<<grid, THREADS, SMEM_BYTES>>>(x, out);
}